// round 16
// baseline (speedup 1.0000x reference)
#include <cuda_runtime.h>
#include <cuda_fp16.h>
#include <mma.h>
using namespace nvcuda;

#define NB 4
#define NC 64
#define NN 8192
#define NK 16
#define NO 64
#define EPSV 1e-5f

// Combined y, fp16: [b][n][128] halves. ch 0-63  = y1 = inv*(W1-W2)@x  (gather via e1)
//                                      ch 64-127 = y2 = inv*W2@x + shift (gather via e0)
__device__ __align__(16) __half g_y[(size_t)NB * NN * 128];
// Folded weights, fp16, [c][o] (row-major, ldb=128): o<64 -> (W1-W2)*inv, o>=64 -> W2*inv.
__device__ __align__(16) __half g_Wf[64 * 128];

#define XH_LD 72    // sXh [c][n] fp16 rows (64 + 8 pad)
#define ST_LD 40    // epilogue staging row stride (floats)

// smem: [0, 10240) = union( X tile 64*72*2=9216 , staging 4*16*40*4=10240 )
//       [10240, 10752) = shift table (128 floats)
#define SMEM_SHIFT 10240
#define SMEM_TOT   10752

// ---------------------------------------------------------------------------
// kW: fold BN into W once -> g_Wf fp16 [c][o]. 8192 items.
// ---------------------------------------------------------------------------
__global__ __launch_bounds__(256) void kW(
    const float* __restrict__ W, const float* __restrict__ gamma,
    const float* __restrict__ rvar)
{
    int idx = blockIdx.x * 256 + threadIdx.x;   // grid 32 x 256 = 8192
    int c = idx >> 7, o = idx & 127;
    int o2 = (o < 64) ? o : (o - 64);
    float inv = gamma[o2] * rsqrtf(rvar[o2] + EPSV);
    float v;
    if (o < 64) v = (W[o2 * 128 + c] - W[o2 * 128 + 64 + c]) * inv;
    else        v = W[o2 * 128 + 64 + c] * inv;
    g_Wf[c * 128 + o] = __float2half_rn(v);
}

// ---------------------------------------------------------------------------
// Kernel A (tensor cores): 64-node x 128-out block, 128 threads (4 warps).
// B fragments loaded straight from global g_Wf (L1/L2-hot, 16KB) -> no W
// smem, ~10.5KB smem total -> 4-5 blocks/SM (was 2): block-internal
// latency chains (stage->MMA->epilogue) now overlap across blocks.
// ---------------------------------------------------------------------------
__global__ __launch_bounds__(128) void kA(
    const float* __restrict__ x,
    const float* __restrict__ gamma, const float* __restrict__ beta,
    const float* __restrict__ rmean, const float* __restrict__ rvar)
{
    __shared__ __align__(16) char smem[SMEM_TOT];
    __half* sXh    = (__half*)smem;
    float*  sshift = (float*)(smem + SMEM_SHIFT);

    const int tid  = threadIdx.x;
    const int b    = blockIdx.y;
    const int n0b  = blockIdx.x * 64;
    const int w    = tid >> 5;
    const int lane = tid & 31;

    // BN shift table (y2 half only).
    {
        float s = 0.f;
        if (tid >= 64) {
            int o2 = tid - 64;
            s = beta[o2] - rmean[o2] * gamma[o2] * rsqrtf(rvar[o2] + EPSV);
        }
        sshift[tid] = s;
    }

    // Stage X tile: [64 c][64 n] fp32 -> fp16, 8 float4 per thread, coalesced.
    {
        const float4* xp = (const float4*)(x + (size_t)b * NC * NN + n0b);
#pragma unroll
        for (int it = 0; it < 8; it++) {
            int i = it * 128 + tid;
            int c = i >> 4, j = i & 15;
            float4 v = xp[(size_t)c * (NN / 4) + j];
            __half2* dst = (__half2*)&sXh[c * XH_LD + 4 * j];
            dst[0] = __floats2half2_rn(v.x, v.y);
            dst[1] = __floats2half2_rn(v.z, v.w);
        }
    }
    __syncthreads();

    // Mainloop: warp w covers nodes [w*16, +16), all 128 outs.
    const int n0 = w * 16;
    wmma::fragment<wmma::matrix_a, 16, 16, 16, __half, wmma::col_major> af;
    wmma::fragment<wmma::matrix_b, 16, 16, 16, __half, wmma::row_major> bf;
    wmma::fragment<wmma::accumulator, 16, 16, 16, float> acc[8];
#pragma unroll
    for (int t = 0; t < 8; t++) wmma::fill_fragment(acc[t], 0.0f);

#pragma unroll
    for (int k = 0; k < 4; k++) {
        wmma::load_matrix_sync(af, sXh + k * 16 * XH_LD + n0, XH_LD);
        const __half* wrow = g_Wf + k * 16 * 128;
#pragma unroll
        for (int t = 0; t < 8; t++) {
            wmma::load_matrix_sync(bf, wrow + t * 16, 128);   // global, L1-hot
            wmma::mma_sync(acc[t], af, bf, acc[t]);
        }
    }
    __syncthreads();   // smem (X region) reused for epilogue staging

    // Epilogue (R10-proven): 4 passes of 32 outs via per-warp smem staging.
    float* st = (float*)smem + w * 16 * ST_LD;
    const int r = lane & 15, h = lane >> 4;
#pragma unroll
    for (int p = 0; p < 4; p++) {
        wmma::store_matrix_sync(st,      acc[2 * p],     ST_LD, wmma::mem_row_major);
        wmma::store_matrix_sync(st + 16, acc[2 * p + 1], ST_LD, wmma::mem_row_major);
        __syncwarp();
        int ob = p * 32 + h * 16;
        const float* row = st + r * ST_LD + h * 16;
        __half2 hh[8];
#pragma unroll
        for (int j = 0; j < 4; j++) {
            float4 f = *(const float4*)(row + 4 * j);
            float4 s = *(const float4*)(sshift + ob + 4 * j);
            hh[2 * j]     = __floats2half2_rn(f.x + s.x, f.y + s.y);
            hh[2 * j + 1] = __floats2half2_rn(f.z + s.z, f.w + s.w);
        }
        int n = n0b + n0 + r;
        *(uint4*)(&g_y[(((size_t)b * NN + n) << 7) + ob])     = *(uint4*)&hh[0];
        *(uint4*)(&g_y[(((size_t)b * NN + n) << 7) + ob + 8]) = *(uint4*)&hh[4];
        __syncwarp();
    }
}

// ---------------------------------------------------------------------------
// Kernel B: R14 best (wide __ldcg gathers, 14.66us) — unchanged.
// ---------------------------------------------------------------------------
__global__ __launch_bounds__(256) void kB(
    const int* __restrict__ ei, float* __restrict__ out)
{
    __shared__ int  sIdx[1024];      // [0:512) e0 rows, [512:1024) e1 rows
    __shared__ float sm[64 * 33];

    const int tid  = threadIdx.x;
    const int w    = tid >> 5;
    const int lane = tid & 31;
    const int b    = blockIdx.y;
    const int n0   = blockIdx.x * 32;

    const int* e0 = ei + (size_t)b * NN * NK + (size_t)n0 * NK;
    const int* e1 = e0 + (size_t)NB * NN * NK;

    if (tid < 128) ((int4*)sIdx)[tid] = ((const int4*)e0)[tid];
    else           ((int4*)sIdx)[tid] = ((const int4*)e1)[tid - 128];
    __syncthreads();

    const char* yb = (const char*)g_y + ((size_t)b * NN * 256);
    const __half2 NEGI  = __half2half2(__ushort_as_half(0xFC00));
    const __half2 SLOPE = __float2half2_rn(0.2f);

    const int nl  = w * 4 + (lane >> 3);
    const int sub = lane & 7;
    const int* i0p = &sIdx[nl * NK];
    const int* i1p = &sIdx[512 + nl * NK];

    __half2 m[4] = {NEGI, NEGI, NEGI, NEGI};
#pragma unroll
    for (int k = 0; k < 16; k++) {
        int i0 = i0p[k];
        int i1 = i1p[k];
        uint4 av = __ldcg((const uint4*)(yb + (i1 << 8) + (sub << 4)));        // y1
        uint4 cv = __ldcg((const uint4*)(yb + (i0 << 8) + 128 + (sub << 4)));  // y2
        const __half2* a = (const __half2*)&av;
        const __half2* c = (const __half2*)&cv;
#pragma unroll
        for (int q = 0; q < 4; q++) {
            __half2 hq = __hadd2(a[q], c[q]);
            hq = __hmax2(hq, __hmul2(hq, SLOPE));
            m[q] = __hmax2(m[q], hq);
        }
    }
#pragma unroll
    for (int q = 0; q < 4; q++) {
        float2 f = __half22float2(m[q]);
        sm[(sub * 8 + 2 * q)     * 33 + nl] = f.x;
        sm[(sub * 8 + 2 * q + 1) * 33 + nl] = f.y;
    }
    __syncthreads();

#pragma unroll
    for (int i = 0; i < 8; i++) {
        int o = i * 8 + w;
        out[((size_t)(b * NO + o)) * NN + n0 + lane] = sm[o * 33 + lane];
    }
}

extern "C" void kernel_launch(void* const* d_in, const int* in_sizes, int n_in,
                              void* d_out, int out_size)
{
    const float* x     = (const float*)d_in[0];
    const int*   ei    = (const int*)d_in[1];
    const float* W     = (const float*)d_in[2];
    const float* gamma = (const float*)d_in[3];
    const float* beta  = (const float*)d_in[4];
    const float* rmean = (const float*)d_in[5];
    const float* rvar  = (const float*)d_in[6];
    float*       out   = (float*)d_out;

    kW<<<32, 256>>>(W, gamma, rvar);
    kA<<<dim3(NN / 64, NB), 128>>>(x, gamma, beta, rmean, rvar);
    kB<<<dim3(NN / 32, NB), 256>>>(ei, out);
}

// round 17
// speedup vs baseline: 1.2479x; 1.2479x over previous
#include <cuda_runtime.h>
#include <cuda_fp16.h>
#include <mma.h>
using namespace nvcuda;

#define NB 4
#define NC 64
#define NN 8192
#define NK 16
#define NO 64
#define EPSV 1e-5f

// Combined y, fp16: [b][n][128] halves. ch 0-63  = y1 = inv*(W1-W2)@x  (gather via e1)
//                                      ch 64-127 = y2 = inv*W2@x + shift (gather via e0)
__device__ __align__(16) __half g_y[(size_t)NB * NN * 128];

#define XH_LD 136   // sXh [c][n] fp16 rows (pad 8)
#define WH_LD 136   // sWh [c][o] fp16 rows
#define ST_LD 40    // epilogue staging row stride in floats

#define SMEM_XH    0                      // 64*136*2 = 17408
#define SMEM_WH    17408                  // 64*136*2 = 17408
#define SMEM_SHIFT 34816                  // 128 floats = 512
#define SMEM_TOT   (34816 + 512)

// ---------------------------------------------------------------------------
// Kernel A (tensor cores, R10-exact — best measured ~10.1us):
// 128-node x 128-out block, 8 warps, warp = 16 nodes x 128 outs.
// ---------------------------------------------------------------------------
__global__ __launch_bounds__(256, 2) void kA(
    const float* __restrict__ x, const float* __restrict__ W,
    const float* __restrict__ gamma, const float* __restrict__ beta,
    const float* __restrict__ rmean, const float* __restrict__ rvar)
{
    __shared__ __align__(16) char smem[SMEM_TOT];
    __half* sXh    = (__half*)(smem + SMEM_XH);
    __half* sWh    = (__half*)(smem + SMEM_WH);
    float*  sshift = (float*)(smem + SMEM_SHIFT);
    __shared__ float sinv[64];

    const int tid = threadIdx.x;
    const int b   = blockIdx.y;
    const int n0b = blockIdx.x * 128;
    const int w   = tid >> 5;
    const int lane = tid & 31;

    if (tid < 64) sinv[tid] = gamma[tid] * rsqrtf(rvar[tid] + EPSV);
    if (tid < 128) {
        float s = 0.f;
        if (tid >= 64) {
            int o2 = tid - 64;
            s = beta[o2] - rmean[o2] * gamma[o2] * rsqrtf(rvar[o2] + EPSV);
        }
        sshift[tid] = s;
    }

    {
        const float4* xp = (const float4*)(x + (size_t)b * NC * NN + n0b);
        for (int i = tid; i < 64 * 32; i += 256) {
            int c = i >> 5, j = i & 31;
            float4 v = xp[(size_t)c * (NN / 4) + j];
            __half2 h0 = __floats2half2_rn(v.x, v.y);
            __half2 h1 = __floats2half2_rn(v.z, v.w);
            __half2* dst = (__half2*)&sXh[c * XH_LD + 4 * j];
            dst[0] = h0; dst[1] = h1;
        }
    }
    __syncthreads();

    for (int i = tid; i < 2048; i += 256) {
        int q = i >> 6, c = i & 63;
        int o0 = q * 4;
        float v[4];
        if (o0 < 64) {
#pragma unroll
            for (int j = 0; j < 4; j++) {
                int o = o0 + j;
                v[j] = (W[o * 128 + c] - W[o * 128 + 64 + c]) * sinv[o];
            }
        } else {
#pragma unroll
            for (int j = 0; j < 4; j++) {
                int o2 = o0 + j - 64;
                v[j] = W[o2 * 128 + 64 + c] * sinv[o2];
            }
        }
        __half2* dst = (__half2*)&sWh[c * WH_LD + o0];
        dst[0] = __floats2half2_rn(v[0], v[1]);
        dst[1] = __floats2half2_rn(v[2], v[3]);
    }
    __syncthreads();

    const int n0 = w * 16;
    wmma::fragment<wmma::matrix_a, 16, 16, 16, __half, wmma::col_major> af;
    wmma::fragment<wmma::matrix_b, 16, 16, 16, __half, wmma::row_major> bf;
    wmma::fragment<wmma::accumulator, 16, 16, 16, float> acc[8];
#pragma unroll
    for (int t = 0; t < 8; t++) wmma::fill_fragment(acc[t], 0.0f);

#pragma unroll
    for (int k = 0; k < 4; k++) {
        wmma::load_matrix_sync(af, sXh + k * 16 * XH_LD + n0, XH_LD);
#pragma unroll
        for (int t = 0; t < 8; t++) {
            wmma::load_matrix_sync(bf, sWh + k * 16 * WH_LD + t * 16, WH_LD);
            wmma::mma_sync(acc[t], af, bf, acc[t]);
        }
    }
    __syncthreads();

    float* st = (float*)smem + w * 16 * ST_LD;
    const int r = lane & 15, h = lane >> 4;
#pragma unroll
    for (int p = 0; p < 4; p++) {
        wmma::store_matrix_sync(st,      acc[2 * p],     ST_LD, wmma::mem_row_major);
        wmma::store_matrix_sync(st + 16, acc[2 * p + 1], ST_LD, wmma::mem_row_major);
        __syncwarp();
        int ob = p * 32 + h * 16;
        const float* row = st + r * ST_LD + h * 16;
        __half2 hh[8];
#pragma unroll
        for (int j = 0; j < 4; j++) {
            float4 f = *(const float4*)(row + 4 * j);
            float4 s = *(const float4*)(sshift + ob + 4 * j);
            hh[2 * j]     = __floats2half2_rn(f.x + s.x, f.y + s.y);
            hh[2 * j + 1] = __floats2half2_rn(f.z + s.z, f.w + s.w);
        }
        int n = n0b + n0 + r;
        *(uint4*)(&g_y[(((size_t)b * NN + n) << 7) + ob])     = *(uint4*)&hh[0];
        *(uint4*)(&g_y[(((size_t)b * NN + n) << 7) + ob + 8]) = *(uint4*)&hh[4];
        __syncwarp();
    }
}

// ---------------------------------------------------------------------------
// Kernel B: wide __ldcg gathers + 6-blocks/SM reg cap (42 regs) for one
// extra resident block of latency hiding (was reg-capped at 5 blocks @44).
// ---------------------------------------------------------------------------
__global__ __launch_bounds__(256, 6) void kB(
    const int* __restrict__ ei, float* __restrict__ out)
{
    __shared__ int  sIdx[1024];      // [0:512) e0 rows, [512:1024) e1 rows
    __shared__ float sm[64 * 33];

    const int tid  = threadIdx.x;
    const int w    = tid >> 5;
    const int lane = tid & 31;
    const int b    = blockIdx.y;
    const int n0   = blockIdx.x * 32;

    const int* e0 = ei + (size_t)b * NN * NK + (size_t)n0 * NK;
    const int* e1 = e0 + (size_t)NB * NN * NK;

    if (tid < 128) ((int4*)sIdx)[tid] = ((const int4*)e0)[tid];
    else           ((int4*)sIdx)[tid] = ((const int4*)e1)[tid - 128];
    __syncthreads();

    const char* yb = (const char*)g_y + ((size_t)b * NN * 256);
    const __half2 NEGI  = __half2half2(__ushort_as_half(0xFC00));
    const __half2 SLOPE = __float2half2_rn(0.2f);

    const int nl  = w * 4 + (lane >> 3);
    const int sub = lane & 7;
    const int* i0p = &sIdx[nl * NK];
    const int* i1p = &sIdx[512 + nl * NK];

    __half2 m[4] = {NEGI, NEGI, NEGI, NEGI};
#pragma unroll
    for (int k = 0; k < 16; k++) {
        int i0 = i0p[k];
        int i1 = i1p[k];
        uint4 av = __ldcg((const uint4*)(yb + (i1 << 8) + (sub << 4)));        // y1
        uint4 cv = __ldcg((const uint4*)(yb + (i0 << 8) + 128 + (sub << 4)));  // y2
        const __half2* a = (const __half2*)&av;
        const __half2* c = (const __half2*)&cv;
#pragma unroll
        for (int q = 0; q < 4; q++) {
            __half2 hq = __hadd2(a[q], c[q]);
            hq = __hmax2(hq, __hmul2(hq, SLOPE));
            m[q] = __hmax2(m[q], hq);
        }
    }
#pragma unroll
    for (int q = 0; q < 4; q++) {
        float2 f = __half22float2(m[q]);
        sm[(sub * 8 + 2 * q)     * 33 + nl] = f.x;
        sm[(sub * 8 + 2 * q + 1) * 33 + nl] = f.y;
    }
    __syncthreads();

#pragma unroll
    for (int i = 0; i < 8; i++) {
        int o = i * 8 + w;
        out[((size_t)(b * NO + o)) * NN + n0 + lane] = sm[o * 33 + lane];
    }
}

extern "C" void kernel_launch(void* const* d_in, const int* in_sizes, int n_in,
                              void* d_out, int out_size)
{
    const float* x     = (const float*)d_in[0];
    const int*   ei    = (const int*)d_in[1];
    const float* W     = (const float*)d_in[2];
    const float* gamma = (const float*)d_in[3];
    const float* beta  = (const float*)d_in[4];
    const float* rmean = (const float*)d_in[5];
    const float* rvar  = (const float*)d_in[6];
    float*       out   = (float*)d_out;

    kA<<<dim3(NN / 128, NB), 256>>>(x, W, gamma, beta, rmean, rvar);
    kB<<<dim3(NN / 32, NB), 256>>>(ei, out);
}